// round 5
// baseline (speedup 1.0000x reference)
#include <cuda_runtime.h>

// out = clip(where(mask, 0.05, x), 0, 1), fused into ONE kernel:
//   1) grid-stride saturate-copy (streaming hints; working set > L2)
//   2) last-block-done ticket: the final block (after all copy stores are
//      visible) rasterizes the 192 Bresenham lines directly into out.
// CRACK_VAL=0.05 is inside [0,1], so clip(0.05)=0.05 and the mask branch
// reduces to a plain overwrite.
//
// Reference quirk: inactive Bresenham steps have coords (-1,-1); JAX .at[]
// normalizes negative indices BEFORE mode='drop', so -1 wraps to 511 =>
// every image with any line of nsteps < 511 also gets pixel (511,511) set.

#define HW 512
#define PLANE (HW * HW)
#define LINES_PER_IMG 6
#define N_LINES 192
#define CRACK_VAL 0.05f

#define TPB 1024
#define GRID 296          // 148 SMs * 2

__device__ unsigned int g_done = 0;   // reset by the last block each launch

__global__ void __launch_bounds__(TPB)
fused_crack_kernel(const float4* __restrict__ in, float4* __restrict__ out,
                   int n4, const int* __restrict__ ep) {
    // ---- Phase 1: grid-stride saturate copy ----
    const int stride = GRID * TPB;
    for (int i = blockIdx.x * TPB + threadIdx.x; i < n4; i += stride) {
        float4 v = __ldcs(in + i);
        v.x = __saturatef(v.x);
        v.y = __saturatef(v.y);
        v.z = __saturatef(v.z);
        v.w = __saturatef(v.w);
        __stcs(out + i, v);
    }

    // ---- Ticket: release our stores, grab a ticket ----
    __syncthreads();
    __shared__ int s_last;
    if (threadIdx.x == 0) {
        __threadfence();                            // release block's stores
        unsigned t = atomicAdd(&g_done, 1u);        // ticket
        s_last = (t == GRID - 1);
        if (s_last) {
            g_done = 0;                             // reset for graph replay
            __threadfence();                        // acquire all blocks' stores
        }
    }
    __syncthreads();
    if (!s_last) return;

    // ---- Phase 2 (last block only): rasterize 192 lines ----
    // Closed-form Bresenham matching the reference recurrence
    // (emit-before-step; c1: 2err > -dy -> x+=sx; c2: 2err < dx -> y+=sy):
    //   x-major (dx>=dy): point t = (x0+sx*t, y0+sy*((2t*dy+dx-1)/(2dx)))
    //   y-major: symmetric.
    float* o = (float*)out;
    int warp = threadIdx.x >> 5;   // 0..31
    int lane = threadIdx.x & 31;

    for (int line = warp; line < N_LINES; line += 32) {
        const int* e = ep + line * 4;
        int y0 = e[0], x0 = e[1], y1 = e[2], x1 = e[3];
        int dx = abs(x1 - x0);
        int dy = abs(y1 - y0);
        int sx = (x0 < x1) ? 1 : -1;
        int sy = (y0 < y1) ? 1 : -1;
        int ns = max(dx, dy);

        float* base = o + (size_t)(line / LINES_PER_IMG) * 3 * PLANE;

        // JAX negative-index wrap artifact: inactive steps write (511,511).
        if (lane == 0 && ns < HW - 1) {
            int off = (HW - 1) * HW + (HW - 1);
            base[off]             = CRACK_VAL;
            base[off + PLANE]     = CRACK_VAL;
            base[off + 2 * PLANE] = CRACK_VAL;
        }

        for (int t = lane; t <= ns; t += 32) {
            int xx, yy;
            if (ns == 0) {
                xx = x0; yy = y0;
            } else if (dx >= dy) {
                xx = x0 + sx * t;
                yy = y0 + sy * ((2 * t * dy + dx - 1) / (2 * dx));
            } else {
                yy = y0 + sy * t;
                xx = x0 + sx * ((2 * t * dx + dy - 1) / (2 * dy));
            }
            int off = yy * HW + xx;
            base[off]             = CRACK_VAL;
            base[off + PLANE]     = CRACK_VAL;
            base[off + 2 * PLANE] = CRACK_VAL;
        }
    }
}

extern "C" void kernel_launch(void* const* d_in, const int* in_sizes, int n_in,
                              void* d_out, int out_size) {
    const float* x = (const float*)d_in[0];
    const int* endpoints = (const int*)d_in[1];
    int n4 = out_size / 4;
    fused_crack_kernel<<<GRID, TPB>>>((const float4*)x, (float4*)d_out, n4,
                                      endpoints);
}